// round 1
// baseline (speedup 1.0000x reference)
#include <cuda_runtime.h>

#define NN 40000
#define EE 640000
#define FD 128
#define HH 4
#define LL 3
#define NEG 0.2f
#define BNEPS 1e-5f

// ---------------- scratch (device globals; no allocations allowed) ----------
__device__ __align__(16) float g_h  [NN * FD];   // h = x @ W           [N,128]
__device__ __align__(16) float g_acc[NN * FD];   // aggregation output  [N,128]
__device__ __align__(16) float g_x  [NN * FD];   // layer input ping    [N,128]
__device__ __align__(16) float g_as [NN * HH];   // per-head src logits [N,4]
__device__ __align__(16) float g_ad [NN * HH];   // per-head dst logits [N,4]
__device__ __align__(16) float g_es [NN * HH];   // self-loop raw e     [N,4]
__device__ __align__(16) float g_em [NN * HH];   // segment max         [N,4]
__device__ __align__(16) float g_ws [NN * HH];   // self-loop weight    [N,4]
__device__ __align__(16) float g_dn [NN * HH];   // softmax denom       [N,4]

__device__ __forceinline__ float lrelu(float v) { return v > 0.f ? v : NEG * v; }

__device__ __forceinline__ void atomicMaxF(float* a, float v) {
    if (v >= 0.f) atomicMax((int*)a, __float_as_int(v));
    else          atomicMin((unsigned int*)a, __float_as_uint(v));
}

// ---------------- K1: h = x @ W, plus per-head att logits -------------------
// block: 128 threads, handles 16 rows. warp w == head w for the reduction.
__global__ void k_gemm_att(const float* __restrict__ x_in, int layer,
                           const float* __restrict__ W,
                           const float* __restrict__ as_w,
                           const float* __restrict__ ad_w) {
    const float* x = (layer == 0) ? x_in : g_x;
    __shared__ float xs[16][FD];
    const int tid  = threadIdx.x;
    const int row0 = blockIdx.x * 16;
#pragma unroll
    for (int r = 0; r < 16; r++) xs[r][tid] = x[(row0 + r) * FD + tid];
    __syncthreads();

    float acc[16];
#pragma unroll
    for (int r = 0; r < 16; r++) acc[r] = 0.f;
#pragma unroll 4
    for (int k = 0; k < FD; k++) {
        const float w = W[k * FD + tid];
#pragma unroll
        for (int r = 0; r < 16; r++) acc[r] += xs[r][k] * w;
    }
#pragma unroll
    for (int r = 0; r < 16; r++) g_h[(row0 + r) * FD + tid] = acc[r];

    const int head = tid >> 5, lane = tid & 31;
    const float avs = as_w[tid], avd = ad_w[tid];
#pragma unroll
    for (int r = 0; r < 16; r++) {
        float s = acc[r] * avs;
        float d = acc[r] * avd;
#pragma unroll
        for (int o = 16; o > 0; o >>= 1) {
            s += __shfl_down_sync(0xffffffffu, s, o);
            d += __shfl_down_sync(0xffffffffu, d, o);
        }
        if (lane == 0) {
            g_as[(row0 + r) * HH + head] = s;
            g_ad[(row0 + r) * HH + head] = d;
        }
    }
}

// ---------------- K2a: self-loop logit, init e_max --------------------------
__global__ void k_node_init() {
    int i = blockIdx.x * blockDim.x + threadIdx.x;
    if (i >= NN * HH) return;
    float e = lrelu(g_as[i] + g_ad[i]);
    g_es[i] = e;
    g_em[i] = e;
}

// ---------------- K2b: segment max over edges --------------------------------
__global__ void k_edge_max(const int* __restrict__ src, const int* __restrict__ dst) {
    int e = blockIdx.x * blockDim.x + threadIdx.x;
    if (e >= EE) return;
    const int s = src[e], d = dst[e];
    const float4 as = *(const float4*)&g_as[s * HH];
    const float4 ad = *(const float4*)&g_ad[d * HH];
    float* em = &g_em[d * HH];
    atomicMaxF(em + 0, lrelu(as.x + ad.x));
    atomicMaxF(em + 1, lrelu(as.y + ad.y));
    atomicMaxF(em + 2, lrelu(as.z + ad.z));
    atomicMaxF(em + 3, lrelu(as.w + ad.w));
}

// ---------------- K3a: self-loop weight, init denom --------------------------
__global__ void k_node_denom() {
    int i = blockIdx.x * blockDim.x + threadIdx.x;
    if (i >= NN * HH) return;
    float w = expf(g_es[i] - g_em[i]);
    g_ws[i] = w;
    g_dn[i] = w;
}

// ---------------- K3b: softmax denominator over edges ------------------------
__global__ void k_edge_denom(const int* __restrict__ src, const int* __restrict__ dst) {
    int e = blockIdx.x * blockDim.x + threadIdx.x;
    if (e >= EE) return;
    const int s = src[e], d = dst[e];
    const float4 as = *(const float4*)&g_as[s * HH];
    const float4 ad = *(const float4*)&g_ad[d * HH];
    const float4 em = *(const float4*)&g_em[d * HH];
    float* dn = &g_dn[d * HH];
    atomicAdd(dn + 0, expf(lrelu(as.x + ad.x) - em.x));
    atomicAdd(dn + 1, expf(lrelu(as.y + ad.y) - em.y));
    atomicAdd(dn + 2, expf(lrelu(as.z + ad.z) - em.z));
    atomicAdd(dn + 3, expf(lrelu(as.w + ad.w) - em.w));
}

// ---------------- K4a: init accumulator with self-loop message ---------------
__global__ void k_out_init() {
    int i = blockIdx.x * blockDim.x + threadIdx.x;   // one float4 per thread
    if (i >= NN * 32) return;
    const int n = i >> 5;
    const int q = i & 31;             // float4 index within row
    const int head = q >> 3;          // 8 float4s per head
    const float alpha = g_ws[n * HH + head] / (g_dn[n * HH + head] + 1e-16f);
    float4 hv = *(const float4*)&g_h[i * 4];
    hv.x *= alpha; hv.y *= alpha; hv.z *= alpha; hv.w *= alpha;
    *(float4*)&g_acc[i * 4] = hv;
}

// ---------------- K4b: edge aggregation (warp per edge) ----------------------
__global__ void k_edge_agg(const int* __restrict__ src, const int* __restrict__ dst) {
    const int gt   = blockIdx.x * blockDim.x + threadIdx.x;
    const int e    = gt >> 5;
    const int lane = threadIdx.x & 31;
    if (e >= EE) return;
    const int s = src[e], d = dst[e];
    const int head = lane >> 3;                      // 8 lanes per head
    const float ev    = lrelu(g_as[s * HH + head] + g_ad[d * HH + head]);
    const float alpha = expf(ev - g_em[d * HH + head]) / (g_dn[d * HH + head] + 1e-16f);
    const float4 hv = *(const float4*)&g_h[s * FD + lane * 4];
    float* po = &g_acc[d * FD + lane * 4];
    asm volatile("red.global.add.v4.f32 [%0], {%1, %2, %3, %4};"
                 :: "l"(po), "f"(hv.x * alpha), "f"(hv.y * alpha),
                    "f"(hv.z * alpha), "f"(hv.w * alpha)
                 : "memory");
}

// ---------------- K5: bias + BN(eval) + ReLU -> next layer input -------------
__global__ void k_epilogue(const float* __restrict__ bias,
                           const float* __restrict__ gamma,
                           const float* __restrict__ beta,
                           const float* __restrict__ mean,
                           const float* __restrict__ var) {
    int i = blockIdx.x * blockDim.x + threadIdx.x;   // one float4 per thread
    if (i >= NN * 32) return;
    const int c4 = (i & 31) * 4;
    float4 v  = *(const float4*)&g_acc[i * 4];
    const float4 b  = *(const float4*)&bias[c4];
    const float4 g  = *(const float4*)&gamma[c4];
    const float4 bt = *(const float4*)&beta[c4];
    const float4 m  = *(const float4*)&mean[c4];
    const float4 vr = *(const float4*)&var[c4];
    float4 o;
    o.x = (v.x + b.x - m.x) * rsqrtf(vr.x + BNEPS) * g.x + bt.x;
    o.y = (v.y + b.y - m.y) * rsqrtf(vr.y + BNEPS) * g.y + bt.y;
    o.z = (v.z + b.z - m.z) * rsqrtf(vr.z + BNEPS) * g.z + bt.z;
    o.w = (v.w + b.w - m.w) * rsqrtf(vr.w + BNEPS) * g.w + bt.w;
    o.x = fmaxf(o.x, 0.f); o.y = fmaxf(o.y, 0.f);
    o.z = fmaxf(o.z, 0.f); o.w = fmaxf(o.w, 0.f);
    *(float4*)&g_x[i * 4] = o;
}

// ---------------- K6: final projection to scalar per node --------------------
__global__ void k_final(const float* __restrict__ w_out,
                        const float* __restrict__ b_out,
                        float* __restrict__ out) {
    const int gt   = blockIdx.x * blockDim.x + threadIdx.x;
    const int n    = gt >> 5;
    const int lane = threadIdx.x & 31;
    if (n >= NN) return;
    const float4 xv = *(const float4*)&g_x[n * FD + lane * 4];
    const float4 wv = *(const float4*)&w_out[lane * 4];
    float sum = xv.x * wv.x + xv.y * wv.y + xv.z * wv.z + xv.w * wv.w;
#pragma unroll
    for (int o = 16; o > 0; o >>= 1) sum += __shfl_down_sync(0xffffffffu, sum, o);
    if (lane == 0) out[n] = sum + b_out[0];
}

// ---------------- launcher ---------------------------------------------------
extern "C" void kernel_launch(void* const* d_in, const int* in_sizes, int n_in,
                              void* d_out, int out_size) {
    const float* x       = (const float*)d_in[0];
    const int*   ei      = (const int*)  d_in[1];
    const float* W       = (const float*)d_in[2];
    const float* att_src = (const float*)d_in[3];
    const float* att_dst = (const float*)d_in[4];
    const float* bias    = (const float*)d_in[5];
    const float* gamma   = (const float*)d_in[6];
    const float* beta    = (const float*)d_in[7];
    const float* mean    = (const float*)d_in[8];
    const float* var     = (const float*)d_in[9];
    const float* w_out   = (const float*)d_in[10];
    const float* b_out   = (const float*)d_in[11];

    const int* src = ei;
    const int* dst = ei + EE;

    const int TB = 256;
    for (int l = 0; l < LL; l++) {
        k_gemm_att <<<NN / 16, 128>>>(x, l, W + l * FD * FD,
                                      att_src + l * FD, att_dst + l * FD);
        k_node_init <<<(NN * HH + TB - 1) / TB, TB>>>();
        k_edge_max  <<<(EE + TB - 1) / TB, TB>>>(src, dst);
        k_node_denom<<<(NN * HH + TB - 1) / TB, TB>>>();
        k_edge_denom<<<(EE + TB - 1) / TB, TB>>>(src, dst);
        k_out_init  <<<(NN * 32 + TB - 1) / TB, TB>>>();
        k_edge_agg  <<<((long long)EE * 32 + TB - 1) / TB, TB>>>(src, dst);
        k_epilogue  <<<(NN * 32 + TB - 1) / TB, TB>>>(bias + l * FD, gamma + l * FD,
                                                      beta + l * FD, mean + l * FD,
                                                      var + l * FD);
    }
    k_final<<<(NN * 32 + TB - 1) / TB, TB>>>(w_out, b_out, (float*)d_out);
}

// round 2
// speedup vs baseline: 1.6085x; 1.6085x over previous
#include <cuda_runtime.h>

#define NN 40000
#define EE 640000
#define FD 128
#define HH 4
#define LL 3
#define NEG 0.2f
#define BNEPS 1e-5f

// ---------------- scratch (device globals; no allocations allowed) ----------
__device__ __align__(16) float g_h  [NN * FD];     // h = x @ W           [N,128]
__device__ __align__(16) float g_x  [NN * FD];     // layer input ping    [N,128]
__device__ __align__(16) float g_as [NN * HH];     // per-head src logits [N,4]
__device__ __align__(16) float g_ad [NN * HH];     // per-head dst logits [N,4]
__device__ int   g_cnt [NN];                        // in-degree counts
__device__ int   g_rs  [NN + 1];                    // CSR row starts
__device__ int   g_woff[NN];                        // scatter cursors
__device__ int   g_csrc[EE];                        // CSR src node ids
__device__ __align__(16) float g_alpha[EE * HH];    // unnormalized weights

__device__ __forceinline__ float lrelu(float v) { return v > 0.f ? v : NEG * v; }

// ---------------- CSR build --------------------------------------------------
__global__ void k_zero_cnt() {
    int i = blockIdx.x * blockDim.x + threadIdx.x;
    if (i < NN) g_cnt[i] = 0;
}

__global__ void k_hist(const int* __restrict__ dst) {
    int e = blockIdx.x * blockDim.x + threadIdx.x;
    if (e < EE) atomicAdd(&g_cnt[dst[e]], 1);
}

// single block, 1024 threads: exclusive prefix sum over g_cnt -> g_rs, g_woff
__global__ void k_scan() {
    __shared__ int part[1024];
    const int t = threadIdx.x;
    const int CH = 40;                        // 1024*40 = 40960 >= NN
    const int base = t * CH;
    int s = 0;
#pragma unroll 8
    for (int i = 0; i < CH; i++) {
        int idx = base + i;
        if (idx < NN) s += g_cnt[idx];
    }
    part[t] = s;
    __syncthreads();
    for (int o = 1; o < 1024; o <<= 1) {
        int v = (t >= o) ? part[t - o] : 0;
        __syncthreads();
        part[t] += v;
        __syncthreads();
    }
    int excl = (t == 0) ? 0 : part[t - 1];
    for (int i = 0; i < CH; i++) {
        int idx = base + i;
        if (idx < NN) {
            g_rs[idx]   = excl;
            g_woff[idx] = excl;
            excl += g_cnt[idx];
        }
    }
    if (t == 1023) g_rs[NN] = part[1023];
}

__global__ void k_scatter(const int* __restrict__ src, const int* __restrict__ dst) {
    int e = blockIdx.x * blockDim.x + threadIdx.x;
    if (e >= EE) return;
    int p = atomicAdd(&g_woff[dst[e]], 1);
    g_csrc[p] = src[e];
}

// ---------------- K1: h = x @ W, plus per-head att logits -------------------
__global__ void k_gemm_att(const float* __restrict__ x_in, int layer,
                           const float* __restrict__ W,
                           const float* __restrict__ as_w,
                           const float* __restrict__ ad_w) {
    const float* x = (layer == 0) ? x_in : g_x;
    __shared__ float xs[16][FD];
    const int tid  = threadIdx.x;
    const int row0 = blockIdx.x * 16;
#pragma unroll
    for (int r = 0; r < 16; r++) xs[r][tid] = x[(row0 + r) * FD + tid];
    __syncthreads();

    float acc[16];
#pragma unroll
    for (int r = 0; r < 16; r++) acc[r] = 0.f;
#pragma unroll 4
    for (int k = 0; k < FD; k++) {
        const float w = W[k * FD + tid];
#pragma unroll
        for (int r = 0; r < 16; r++) acc[r] += xs[r][k] * w;
    }
#pragma unroll
    for (int r = 0; r < 16; r++) g_h[(row0 + r) * FD + tid] = acc[r];

    const int head = tid >> 5, lane = tid & 31;
    const float avs = as_w[tid], avd = ad_w[tid];
#pragma unroll
    for (int r = 0; r < 16; r++) {
        float s = acc[r] * avs;
        float d = acc[r] * avd;
#pragma unroll
        for (int o = 16; o > 0; o >>= 1) {
            s += __shfl_down_sync(0xffffffffu, s, o);
            d += __shfl_down_sync(0xffffffffu, d, o);
        }
        if (lane == 0) {
            g_as[(row0 + r) * HH + head] = s;
            g_ad[(row0 + r) * HH + head] = d;
        }
    }
}

// ---------------- K2: fused attention softmax + aggregation + epilogue ------
// one warp per destination node; no atomics anywhere.
__global__ void k_attn_agg(int last,
                           const float* __restrict__ bias,
                           const float* __restrict__ gamma,
                           const float* __restrict__ beta,
                           const float* __restrict__ mean,
                           const float* __restrict__ var,
                           const float* __restrict__ w_out,
                           const float* __restrict__ b_out,
                           float* __restrict__ out) {
    const int n    = (blockIdx.x * blockDim.x + threadIdx.x) >> 5;
    const int lane = threadIdx.x & 31;
    if (n >= NN) return;
    const int rs = g_rs[n], re = g_rs[n + 1];

    const float4 adv = *(const float4*)&g_ad[n * HH];
    const float4 asn = *(const float4*)&g_as[n * HH];

    // self-loop logits per head
    float es0 = lrelu(asn.x + adv.x);
    float es1 = lrelu(asn.y + adv.y);
    float es2 = lrelu(asn.z + adv.z);
    float es3 = lrelu(asn.w + adv.w);

    // ---- pass 1: segment max (lanes parallel over edges) ----
    float m0 = es0, m1 = es1, m2 = es2, m3 = es3;
    for (int j = rs + lane; j < re; j += 32) {
        const int s = g_csrc[j];
        const float4 as = *(const float4*)&g_as[s * HH];
        m0 = fmaxf(m0, lrelu(as.x + adv.x));
        m1 = fmaxf(m1, lrelu(as.y + adv.y));
        m2 = fmaxf(m2, lrelu(as.z + adv.z));
        m3 = fmaxf(m3, lrelu(as.w + adv.w));
    }
#pragma unroll
    for (int o = 16; o > 0; o >>= 1) {
        m0 = fmaxf(m0, __shfl_xor_sync(0xffffffffu, m0, o));
        m1 = fmaxf(m1, __shfl_xor_sync(0xffffffffu, m1, o));
        m2 = fmaxf(m2, __shfl_xor_sync(0xffffffffu, m2, o));
        m3 = fmaxf(m3, __shfl_xor_sync(0xffffffffu, m3, o));
    }

    // ---- pass 2: exp-sum, store unnormalized weights ----
    float s0 = 0.f, s1 = 0.f, s2 = 0.f, s3 = 0.f;
    if (lane == 0) {                       // self-loop contribution once
        s0 = expf(es0 - m0); s1 = expf(es1 - m1);
        s2 = expf(es2 - m2); s3 = expf(es3 - m3);
    }
    for (int j = rs + lane; j < re; j += 32) {
        const int s = g_csrc[j];
        const float4 as = *(const float4*)&g_as[s * HH];
        float4 w;
        w.x = expf(lrelu(as.x + adv.x) - m0);
        w.y = expf(lrelu(as.y + adv.y) - m1);
        w.z = expf(lrelu(as.z + adv.z) - m2);
        w.w = expf(lrelu(as.w + adv.w) - m3);
        *(float4*)&g_alpha[j * HH] = w;
        s0 += w.x; s1 += w.y; s2 += w.z; s3 += w.w;
    }
#pragma unroll
    for (int o = 16; o > 0; o >>= 1) {
        s0 += __shfl_xor_sync(0xffffffffu, s0, o);
        s1 += __shfl_xor_sync(0xffffffffu, s1, o);
        s2 += __shfl_xor_sync(0xffffffffu, s2, o);
        s3 += __shfl_xor_sync(0xffffffffu, s3, o);
    }
    const float i0 = 1.f / (s0 + 1e-16f);
    const float i1 = 1.f / (s1 + 1e-16f);
    const float i2 = 1.f / (s2 + 1e-16f);
    const float i3 = 1.f / (s3 + 1e-16f);

    // ---- pass 3: aggregation (lanes parallel over features) ----
    const int head = lane >> 3;
    const float inv_h = (head == 0) ? i0 : (head == 1) ? i1 : (head == 2) ? i2 : i3;
    const float m_h   = (head == 0) ? m0 : (head == 1) ? m1 : (head == 2) ? m2 : m3;
    const float es_h  = (head == 0) ? es0 : (head == 1) ? es1 : (head == 2) ? es2 : es3;

    const float a_self = expf(es_h - m_h) * inv_h;
    float4 acc = *(const float4*)&g_h[n * FD + lane * 4];
    acc.x *= a_self; acc.y *= a_self; acc.z *= a_self; acc.w *= a_self;

    int s_cur = (rs < re) ? g_csrc[rs] : 0;      // prefetched src
    for (int j = rs; j < re; j++) {
        const int s_next = (j + 1 < re) ? g_csrc[j + 1] : 0;
        const float a = g_alpha[j * HH + head] * inv_h;
        const float4 hv = *(const float4*)&g_h[s_cur * FD + lane * 4];
        acc.x += hv.x * a; acc.y += hv.y * a;
        acc.z += hv.z * a; acc.w += hv.w * a;
        s_cur = s_next;
    }

    // ---- fused epilogue: bias + BN(eval) + ReLU ----
    const int c4 = lane * 4;
    const float4 b  = *(const float4*)&bias[c4];
    const float4 g  = *(const float4*)&gamma[c4];
    const float4 bt = *(const float4*)&beta[c4];
    const float4 mm = *(const float4*)&mean[c4];
    const float4 vr = *(const float4*)&var[c4];
    float4 o;
    o.x = fmaxf((acc.x + b.x - mm.x) * rsqrtf(vr.x + BNEPS) * g.x + bt.x, 0.f);
    o.y = fmaxf((acc.y + b.y - mm.y) * rsqrtf(vr.y + BNEPS) * g.y + bt.y, 0.f);
    o.z = fmaxf((acc.z + b.z - mm.z) * rsqrtf(vr.z + BNEPS) * g.z + bt.z, 0.f);
    o.w = fmaxf((acc.w + b.w - mm.w) * rsqrtf(vr.w + BNEPS) * g.w + bt.w, 0.f);

    if (!last) {
        *(float4*)&g_x[n * FD + c4] = o;
    } else {
        // fused final projection: dot(x_row, w_out) + b_out
        const float4 wv = *(const float4*)&w_out[c4];
        float sum = o.x * wv.x + o.y * wv.y + o.z * wv.z + o.w * wv.w;
#pragma unroll
        for (int off = 16; off > 0; off >>= 1)
            sum += __shfl_down_sync(0xffffffffu, sum, off);
        if (lane == 0) out[n] = sum + b_out[0];
    }
}

// ---------------- launcher ---------------------------------------------------
extern "C" void kernel_launch(void* const* d_in, const int* in_sizes, int n_in,
                              void* d_out, int out_size) {
    const float* x       = (const float*)d_in[0];
    const int*   ei      = (const int*)  d_in[1];
    const float* W       = (const float*)d_in[2];
    const float* att_src = (const float*)d_in[3];
    const float* att_dst = (const float*)d_in[4];
    const float* bias    = (const float*)d_in[5];
    const float* gamma   = (const float*)d_in[6];
    const float* beta    = (const float*)d_in[7];
    const float* mean    = (const float*)d_in[8];
    const float* var     = (const float*)d_in[9];
    const float* w_out   = (const float*)d_in[10];
    const float* b_out   = (const float*)d_in[11];

    const int* src = ei;
    const int* dst = ei + EE;

    // CSR build (edge structure is identical every call)
    k_zero_cnt<<<(NN + 255) / 256, 256>>>();
    k_hist    <<<(EE + 255) / 256, 256>>>(dst);
    k_scan    <<<1, 1024>>>();
    k_scatter <<<(EE + 255) / 256, 256>>>(src, dst);

    for (int l = 0; l < LL; l++) {
        k_gemm_att<<<NN / 16, 128>>>(x, l, W + l * FD * FD,
                                     att_src + l * FD, att_dst + l * FD);
        k_attn_agg<<<(NN * 32 + 255) / 256, 256>>>(
            l == LL - 1,
            bias + l * FD, gamma + l * FD, beta + l * FD,
            mean + l * FD, var + l * FD,
            w_out, b_out, (float*)d_out);
    }
}